// round 1
// baseline (speedup 1.0000x reference)
#include <cuda_runtime.h>
#include <cstdint>

// ---------------------------------------------------------------------------
// QuantumLayer: state stays confined to indices {0,1}; everything else is
// reproducing jax.random.normal(key(42)) noise + row normalization.
// ---------------------------------------------------------------------------

__device__ float2   g_amp[2];      // amplitude at index 0 (e) and 1 (o)
__device__ uint32_t g_keys[4];     // key_re (2), key_im (2) from foldlike split
__device__ float    g_partials[2048];

// ----------------------------- complex helpers -----------------------------
__device__ __forceinline__ float2 cmul(float2 a, float2 b) {
    return make_float2(a.x * b.x - a.y * b.y, a.x * b.y + a.y * b.x);
}
__device__ __forceinline__ float2 cadd(float2 a, float2 b) {
    return make_float2(a.x + b.x, a.y + b.y);
}

// ----------------------------- threefry-2x32 -------------------------------
__device__ __forceinline__ uint2 threefry2x32(uint32_t k0, uint32_t k1,
                                              uint32_t x0, uint32_t x1) {
    uint32_t ks2 = 0x1BD11BDAu ^ k0 ^ k1;
#define TF_R(r) { x0 += x1; x1 = __funnelshift_l(x1, x1, (r)); x1 ^= x0; }
    x0 += k0;  x1 += k1;
    TF_R(13) TF_R(15) TF_R(26) TF_R(6)
    x0 += k1;  x1 += ks2 + 1u;
    TF_R(17) TF_R(29) TF_R(16) TF_R(24)
    x0 += ks2; x1 += k0 + 2u;
    TF_R(13) TF_R(15) TF_R(26) TF_R(6)
    x0 += k0;  x1 += k1 + 3u;
    TF_R(17) TF_R(29) TF_R(16) TF_R(24)
    x0 += k1;  x1 += ks2 + 4u;
    TF_R(13) TF_R(15) TF_R(26) TF_R(6)
    x0 += ks2; x1 += k0 + 5u;
#undef TF_R
    return make_uint2(x0, x1);
}

// ----------------------------- XLA erf_inv (f32) ---------------------------
__device__ __forceinline__ float xla_erfinv(float x) {
    float w = -log1pf(-x * x);
    float p;
    if (w < 5.0f) {
        w -= 2.5f;
        p = 2.81022636e-08f;
        p = fmaf(p, w, 3.43273939e-07f);
        p = fmaf(p, w, -3.5233877e-06f);
        p = fmaf(p, w, -4.39150654e-06f);
        p = fmaf(p, w, 0.00021858087f);
        p = fmaf(p, w, -0.00125372503f);
        p = fmaf(p, w, -0.00417768164f);
        p = fmaf(p, w, 0.246640727f);
        p = fmaf(p, w, 1.50140941f);
    } else {
        w = sqrtf(w) - 3.0f;
        p = -0.000200214257f;
        p = fmaf(p, w, 0.000100950558f);
        p = fmaf(p, w, 0.00134934322f);
        p = fmaf(p, w, -0.00367342844f);
        p = fmaf(p, w, 0.00573950773f);
        p = fmaf(p, w, -0.0076224613f);
        p = fmaf(p, w, 0.00943887047f);
        p = fmaf(p, w, 1.00167406f);
        p = fmaf(p, w, 2.83297682f);
    }
    return p * x;
}

// ---------------------------------------------------------------------------
// K1: build the 78 effective 2x2 matrices (aliasing bug folded in), tree-
// multiply them, store amp = column 0.  Also derive the split keys.
// ---------------------------------------------------------------------------
__global__ __launch_bounds__(128) void k_prep(const float* __restrict__ rx,
                                              const float* __restrict__ ry,
                                              const float* __restrict__ rz) {
    __shared__ float2 M[128][4];   // m00, m01, m10, m11
    const int t = threadIdx.x;

    float2 m00 = {1.f, 0.f}, m01 = {0.f, 0.f}, m10 = {0.f, 0.f}, m11 = {1.f, 0.f};
    if (t < 78) {
        float a; int axis;
        if (t < 26)      { a = rx[t];      axis = 0; }
        else if (t < 52) { a = ry[t - 26]; axis = 1; }
        else             { a = rz[t - 52]; axis = 2; }
        float h = 0.5f * a, s, c;
        sincosf(h, &s, &c);
        float2 e00, e01, e10, e11;
        if (axis == 0) {        // rx
            e00 = {c, 0.f}; e01 = {0.f, -s}; e10 = {0.f, -s}; e11 = {c, 0.f};
        } else if (axis == 1) { // ry
            e00 = {c, 0.f}; e01 = {-s, 0.f}; e10 = {s, 0.f};  e11 = {c, 0.f};
        } else {                // rz
            e00 = {c, -s};  e01 = {0.f, 0.f}; e10 = {0.f, 0.f}; e11 = {c, s};
        }
        // fold the in-place aliasing: o_new = m10 * e_new + m11 * o
        m00 = e00;
        m01 = e01;
        m10 = cmul(e10, e00);
        m11 = cadd(cmul(e10, e01), e11);
    }
    M[t][0] = m00; M[t][1] = m01; M[t][2] = m10; M[t][3] = m11;
    __syncthreads();

    // tree product, preserving order: slot t <- M[2t+1] * M[2t]  (later * earlier)
    for (int n = 64; n >= 1; n >>= 1) {
        float2 c00, c01, c10, c11;
        if (t < n) {
            float2 b00 = M[2*t][0],   b01 = M[2*t][1],   b10 = M[2*t][2],   b11 = M[2*t][3];
            float2 a00 = M[2*t+1][0], a01 = M[2*t+1][1], a10 = M[2*t+1][2], a11 = M[2*t+1][3];
            c00 = cadd(cmul(a00, b00), cmul(a01, b10));
            c01 = cadd(cmul(a00, b01), cmul(a01, b11));
            c10 = cadd(cmul(a10, b00), cmul(a11, b10));
            c11 = cadd(cmul(a10, b01), cmul(a11, b11));
        }
        __syncthreads();
        if (t < n) { M[t][0] = c00; M[t][1] = c01; M[t][2] = c10; M[t][3] = c11; }
        __syncthreads();
    }

    if (t == 0) {
        g_amp[0] = M[0][0];   // amp at index 0 = total m00
        g_amp[1] = M[0][2];   // amp at index 1 = total m10
        // foldlike split of key(42) = (0, 42):
        uint2 kre = threefry2x32(0u, 42u, 0u, 0u);
        uint2 kim = threefry2x32(0u, 42u, 0u, 1u);
        g_keys[0] = kre.x; g_keys[1] = kre.y;
        g_keys[2] = kim.x; g_keys[3] = kim.y;
    }
}

// ---------------------------------------------------------------------------
// K2: per element j = row*8192 + d:
//   bits = lane0 ^ lane1 of threefry(key, 0, j)   (partitionable random_bits)
//   u    = max(LO, bits_as_float * 2 + LO),  noise = erfinv(u) * 0.01
// write |state| to out, accumulate per-block sum of squares.
// grid = 2048 (256 rows x 8 segments), block = 256, 4 elems/thread.
// ---------------------------------------------------------------------------
__global__ __launch_bounds__(256) void k_noise(float* __restrict__ out) {
    const int t   = threadIdx.x;
    const int bid = blockIdx.x;
    const int row = bid >> 3;
    const int seg = bid & 7;

    const uint32_t kre0 = g_keys[0], kre1 = g_keys[1];
    const uint32_t kim0 = g_keys[2], kim1 = g_keys[3];
    const float2 ampe = g_amp[0];
    const float2 ampo = g_amp[1];
    const float LO = -0.99999994039535522461f;   // nextafter(-1, 0)

    float local = 0.0f;
#pragma unroll
    for (int k = 0; k < 4; k++) {
        int d = seg * 1024 + k * 256 + t;
        uint32_t j = (uint32_t)(row * 8192 + d);

        uint2 br = threefry2x32(kre0, kre1, 0u, j);
        uint2 bi = threefry2x32(kim0, kim1, 0u, j);
        uint32_t bre = br.x ^ br.y;
        uint32_t bim = bi.x ^ bi.y;

        float fre = __uint_as_float((bre >> 9) | 0x3f800000u) - 1.0f;
        float fim = __uint_as_float((bim >> 9) | 0x3f800000u) - 1.0f;
        float ure = fmaxf(LO, fmaf(fre, 2.0f, LO));
        float uim = fmaxf(LO, fmaf(fim, 2.0f, LO));

        float re = xla_erfinv(ure) * 0.01f;
        float im = xla_erfinv(uim) * 0.01f;

        if (d == 0) { re += ampe.x; im += ampe.y; }
        if (d == 1) { re += ampo.x; im += ampo.y; }

        float m2 = fmaf(re, re, im * im);
        local += m2;
        out[j] = sqrtf(m2);
    }

    // block reduction of sum of squares
    __shared__ float warpsum[8];
#pragma unroll
    for (int o = 16; o; o >>= 1) local += __shfl_xor_sync(0xFFFFFFFFu, local, o);
    if ((t & 31) == 0) warpsum[t >> 5] = local;
    __syncthreads();
    if (t < 8) {
        float v = warpsum[t];
#pragma unroll
        for (int o = 4; o; o >>= 1) v += __shfl_xor_sync(0xFFu, v, o);
        if (t == 0) g_partials[bid] = v;
    }
}

// ---------------------------------------------------------------------------
// K3: per row, combine 8 partial sums -> 1/norm, scale magnitudes in place.
// ---------------------------------------------------------------------------
__global__ __launch_bounds__(256) void k_norm(float* __restrict__ out) {
    const int row = blockIdx.x;
    const int t   = threadIdx.x;
    __shared__ float rinv_s;
    if (t == 0) {
        float s = 0.f;
#pragma unroll
        for (int i = 0; i < 8; i++) s += g_partials[row * 8 + i];
        rinv_s = 1.0f / sqrtf(s);
    }
    __syncthreads();
    const float rinv = rinv_s;
    float4* o4 = reinterpret_cast<float4*>(out) + row * 2048;
#pragma unroll
    for (int k = 0; k < 8; k++) {
        float4 v = o4[t + 256 * k];
        v.x *= rinv; v.y *= rinv; v.z *= rinv; v.w *= rinv;
        o4[t + 256 * k] = v;
    }
}

// ---------------------------------------------------------------------------
extern "C" void kernel_launch(void* const* d_in, const int* in_sizes, int n_in,
                              void* d_out, int out_size) {
    // metadata order: x (unused), rx_params, ry_params, rz_params
    const float* rx = (const float*)d_in[1];
    const float* ry = (const float*)d_in[2];
    const float* rz = (const float*)d_in[3];
    float* out = (float*)d_out;

    k_prep <<<1, 128>>>(rx, ry, rz);
    k_noise<<<2048, 256>>>(out);
    k_norm <<<256, 256>>>(out);
}

// round 2
// speedup vs baseline: 1.1538x; 1.1538x over previous
#include <cuda_runtime.h>
#include <cstdint>

// ---------------------------------------------------------------------------
// QuantumLayer fused kernel.
// State stays confined to indices {0,1}; bulk work = jax.random.normal noise
// (threefry2x32 partitionable + XLA erfinv) + per-row normalization.
// One block per row (1024 thr x 8 elems). Warp 0 computes the 78-gate 2x2
// product via ordered shuffle reduce, overlapped with other warps' noise.
// Split keys are input-independent -> computed on host, baked into the graph.
// ---------------------------------------------------------------------------

// ----------------------------- complex helpers -----------------------------
__device__ __forceinline__ float2 cmul(float2 a, float2 b) {
    return make_float2(a.x * b.x - a.y * b.y, a.x * b.y + a.y * b.x);
}
__device__ __forceinline__ float2 cadd(float2 a, float2 b) {
    return make_float2(a.x + b.x, a.y + b.y);
}

struct C2x2 { float2 m00, m01, m10, m11; };

__device__ __forceinline__ C2x2 mmul(const C2x2& A, const C2x2& B) {  // A*B
    C2x2 R;
    R.m00 = cadd(cmul(A.m00, B.m00), cmul(A.m01, B.m10));
    R.m01 = cadd(cmul(A.m00, B.m01), cmul(A.m01, B.m11));
    R.m10 = cadd(cmul(A.m10, B.m00), cmul(A.m11, B.m10));
    R.m11 = cadd(cmul(A.m10, B.m01), cmul(A.m11, B.m11));
    return R;
}

__device__ __forceinline__ float2 shf2(float2 v, int off) {
    return make_float2(__shfl_down_sync(0xFFFFFFFFu, v.x, off),
                       __shfl_down_sync(0xFFFFFFFFu, v.y, off));
}
__device__ __forceinline__ C2x2 shfm(const C2x2& P, int off) {
    C2x2 Q;
    Q.m00 = shf2(P.m00, off); Q.m01 = shf2(P.m01, off);
    Q.m10 = shf2(P.m10, off); Q.m11 = shf2(P.m11, off);
    return Q;
}

// ----------------------------- threefry-2x32 -------------------------------
__device__ __forceinline__ uint2 threefry2x32(uint32_t k0, uint32_t k1,
                                              uint32_t x0, uint32_t x1) {
    uint32_t ks2 = 0x1BD11BDAu ^ k0 ^ k1;
#define TF_R(r) { x0 += x1; x1 = __funnelshift_l(x1, x1, (r)); x1 ^= x0; }
    x0 += k0;  x1 += k1;
    TF_R(13) TF_R(15) TF_R(26) TF_R(6)
    x0 += k1;  x1 += ks2 + 1u;
    TF_R(17) TF_R(29) TF_R(16) TF_R(24)
    x0 += ks2; x1 += k0 + 2u;
    TF_R(13) TF_R(15) TF_R(26) TF_R(6)
    x0 += k0;  x1 += k1 + 3u;
    TF_R(17) TF_R(29) TF_R(16) TF_R(24)
    x0 += k1;  x1 += ks2 + 4u;
    TF_R(13) TF_R(15) TF_R(26) TF_R(6)
    x0 += ks2; x1 += k0 + 5u;
#undef TF_R
    return make_uint2(x0, x1);
}

// ------------------- XLA erf_inv (f32), fast log variant -------------------
__device__ __forceinline__ float xla_erfinv_fast(float x) {
    // w = -log(1 - x^2). For |x| small 1-x^2 rounds to 1 -> w=0; the
    // polynomial is smooth there, so the O(x^2) argument error is harmless.
    float w = -__logf(fmaf(x, -x, 1.0f));
    float p;
    if (w < 5.0f) {
        w -= 2.5f;
        p = 2.81022636e-08f;
        p = fmaf(p, w, 3.43273939e-07f);
        p = fmaf(p, w, -3.5233877e-06f);
        p = fmaf(p, w, -4.39150654e-06f);
        p = fmaf(p, w, 0.00021858087f);
        p = fmaf(p, w, -0.00125372503f);
        p = fmaf(p, w, -0.00417768164f);
        p = fmaf(p, w, 0.246640727f);
        p = fmaf(p, w, 1.50140941f);
    } else {
        w = sqrtf(w) - 3.0f;
        p = -0.000200214257f;
        p = fmaf(p, w, 0.000100950558f);
        p = fmaf(p, w, 0.00134934322f);
        p = fmaf(p, w, -0.00367342844f);
        p = fmaf(p, w, 0.00573950773f);
        p = fmaf(p, w, -0.0076224613f);
        p = fmaf(p, w, 0.00943887047f);
        p = fmaf(p, w, 1.00167406f);
        p = fmaf(p, w, 2.83297682f);
    }
    return p * x;
}

// ---------------------------------------------------------------------------
__global__ __launch_bounds__(1024, 1) void k_fused(
    const float* __restrict__ rx, const float* __restrict__ ry,
    const float* __restrict__ rz, float* __restrict__ out,
    uint32_t kre0, uint32_t kre1, uint32_t kim0, uint32_t kim1) {

    const int t   = threadIdx.x;
    const int row = blockIdx.x;

    // ---- warp 0: ordered product of the 78 effective gate matrices ----
    float2 amp0 = {0.f, 0.f}, amp1 = {0.f, 0.f};
    if (t < 32) {
        const int lane = t;
        const int lo = (lane * 78) >> 5;
        const int hi = ((lane + 1) * 78) >> 5;
        C2x2 P;  // identity
        P.m00 = {1.f, 0.f}; P.m01 = {0.f, 0.f};
        P.m10 = {0.f, 0.f}; P.m11 = {1.f, 0.f};
        for (int g = lo; g < hi; ++g) {
            float a;
            int axis;
            if (g < 26)      { a = __ldg(rx + g);      axis = 0; }
            else if (g < 52) { a = __ldg(ry + g - 26); axis = 1; }
            else             { a = __ldg(rz + g - 52); axis = 2; }
            float s, c;
            sincosf(0.5f * a, &s, &c);
            float2 e00, e01, e10, e11;
            if (axis == 0) {        // rx
                e00 = {c, 0.f}; e01 = {0.f, -s}; e10 = {0.f, -s}; e11 = {c, 0.f};
            } else if (axis == 1) { // ry
                e00 = {c, 0.f}; e01 = {-s, 0.f}; e10 = {s, 0.f};  e11 = {c, 0.f};
            } else {                // rz
                e00 = {c, -s};  e01 = {0.f, 0.f}; e10 = {0.f, 0.f}; e11 = {c, s};
            }
            // fold the reference's in-place aliasing bug:
            // o_new = m10 * e_new + m11 * o
            C2x2 E;
            E.m00 = e00;
            E.m01 = e01;
            E.m10 = cmul(e10, e00);
            E.m11 = cadd(cmul(e10, e01), e11);
            P = mmul(E, P);   // later gate on the left
        }
        // ordered reduce: lane 0 ends with P31 * P30 * ... * P0
        #pragma unroll
        for (int off = 1; off < 32; off <<= 1) {
            C2x2 Q = shfm(P, off);
            if ((lane & (2 * off - 1)) == 0) P = mmul(Q, P);
        }
        amp0.x = __shfl_sync(0xFFFFFFFFu, P.m00.x, 0);
        amp0.y = __shfl_sync(0xFFFFFFFFu, P.m00.y, 0);
        amp1.x = __shfl_sync(0xFFFFFFFFu, P.m10.x, 0);
        amp1.y = __shfl_sync(0xFFFFFFFFu, P.m10.y, 0);
    }

    // ---- noise + magnitude for 8 elements per thread ----
    const float LO = -0.99999994039535522461f;   // nextafter(-1, 0)
    float m2s[8];
    float local = 0.0f;

#pragma unroll
    for (int k = 0; k < 8; k++) {
        const int d = k * 1024 + t;
        const uint32_t j = (uint32_t)(row * 8192 + d);

        uint2 br = threefry2x32(kre0, kre1, 0u, j);
        uint2 bi = threefry2x32(kim0, kim1, 0u, j);
        uint32_t bre = br.x ^ br.y;
        uint32_t bim = bi.x ^ bi.y;

        float fre = __uint_as_float((bre >> 9) | 0x3f800000u) - 1.0f;
        float fim = __uint_as_float((bim >> 9) | 0x3f800000u) - 1.0f;
        float ure = fmaxf(LO, fmaf(fre, 2.0f, LO));
        float uim = fmaxf(LO, fmaf(fim, 2.0f, LO));

        float re = xla_erfinv_fast(ure) * 0.01f;
        float im = xla_erfinv_fast(uim) * 0.01f;

        if (k == 0) {
            if (t == 0)      { re += amp0.x; im += amp0.y; }
            else if (t == 1) { re += amp1.x; im += amp1.y; }
        }

        float m2 = fmaf(re, re, im * im);
        m2s[k] = m2;
        local += m2;
    }

    // ---- block reduction of sum of squares over 1024 threads ----
    __shared__ float wsum[32];
    __shared__ float rinv_s;
#pragma unroll
    for (int o = 16; o; o >>= 1) local += __shfl_xor_sync(0xFFFFFFFFu, local, o);
    if ((t & 31) == 0) wsum[t >> 5] = local;
    __syncthreads();
    if (t < 32) {
        float v = wsum[t];
#pragma unroll
        for (int o = 16; o; o >>= 1) v += __shfl_xor_sync(0xFFFFFFFFu, v, o);
        if (t == 0) rinv_s = rsqrtf(v) * (1.0f / rsqrtf(v) * rsqrtf(v));  // placeholder avoided below
        if (t == 0) rinv_s = 1.0f / sqrtf(v);
    }
    __syncthreads();
    const float rinv = rinv_s;

    // ---- scaled magnitude store (coalesced) ----
#pragma unroll
    for (int k = 0; k < 8; k++) {
        const int j = row * 8192 + k * 1024 + t;
        out[j] = sqrtf(m2s[k]) * rinv;
    }
}

// ------------------------- host-side threefry ------------------------------
static inline uint32_t h_rotl(uint32_t x, int r) { return (x << r) | (x >> (32 - r)); }
static void h_threefry(uint32_t k0, uint32_t k1, uint32_t x0, uint32_t x1,
                       uint32_t* o0, uint32_t* o1) {
    uint32_t ks2 = 0x1BD11BDAu ^ k0 ^ k1;
#define HTF(r) { x0 += x1; x1 = h_rotl(x1, (r)); x1 ^= x0; }
    x0 += k0;  x1 += k1;
    HTF(13) HTF(15) HTF(26) HTF(6)
    x0 += k1;  x1 += ks2 + 1u;
    HTF(17) HTF(29) HTF(16) HTF(24)
    x0 += ks2; x1 += k0 + 2u;
    HTF(13) HTF(15) HTF(26) HTF(6)
    x0 += k0;  x1 += k1 + 3u;
    HTF(17) HTF(29) HTF(16) HTF(24)
    x0 += k1;  x1 += ks2 + 4u;
    HTF(13) HTF(15) HTF(26) HTF(6)
    x0 += ks2; x1 += k0 + 5u;
#undef HTF
    *o0 = x0; *o1 = x1;
}

// ---------------------------------------------------------------------------
extern "C" void kernel_launch(void* const* d_in, const int* in_sizes, int n_in,
                              void* d_out, int out_size) {
    // metadata order: x (unused), rx_params, ry_params, rz_params
    const float* rx = (const float*)d_in[1];
    const float* ry = (const float*)d_in[2];
    const float* rz = (const float*)d_in[3];
    float* out = (float*)d_out;

    // foldlike split of key(42) = (0, 42) -> input-independent constants
    uint32_t kre0, kre1, kim0, kim1;
    h_threefry(0u, 42u, 0u, 0u, &kre0, &kre1);
    h_threefry(0u, 42u, 0u, 1u, &kim0, &kim1);

    k_fused<<<256, 1024>>>(rx, ry, rz, out, kre0, kre1, kim0, kim1);
}